// round 1
// baseline (speedup 1.0000x reference)
#include <cuda_runtime.h>
#include <cuda_bf16.h>
#include <cstdint>

// Problem constants (this dataset instance)
#define GLYPH_DIM 4096
#define PAD_IDX   4096
#define EMB_DIM   20
#define HIDDEN    32
#define MAX_LEN   64
#define HW        1659        // 21 * 79
#define MAX_B     8192

// ---------------------------------------------------------------------------
// Device scratch (no allocations allowed)
// ---------------------------------------------------------------------------
__device__ float g_utab[(GLYPH_DIM + 1) * HIDDEN];   // u_table[g][i] = W_ih @ emb[g] + b_ih + b_hh
__device__ int   g_bag [MAX_B * MAX_LEN];            // int bag per sample (for RNN kernel)

// ---------------------------------------------------------------------------
// K0: precompute u_table  (4097 rows x 32)
// ---------------------------------------------------------------------------
__global__ void utab_kernel(const float* __restrict__ emb,
                            const float* __restrict__ W_ih,
                            const float* __restrict__ b_ih,
                            const float* __restrict__ b_hh)
{
    int warp = (blockIdx.x * blockDim.x + threadIdx.x) >> 5;
    int lane = threadIdx.x & 31;
    if (warp > GLYPH_DIM) return;                    // 4097 rows

    const float* er = emb + (size_t)warp * EMB_DIM;
    float acc = __ldg(&b_ih[lane]) + __ldg(&b_hh[lane]);
#pragma unroll
    for (int k = 0; k < EMB_DIM; k++)
        acc += __ldg(&W_ih[lane * EMB_DIM + k]) * __ldg(&er[k]);
    g_utab[warp * HIDDEN + lane] = acc;
}

// ---------------------------------------------------------------------------
// K1: one CTA per sample.  presence bytes -> bitmap -> prefix -> top-64 bag,
// then write bag (float + int scratch) and gathered emb rows.
// ---------------------------------------------------------------------------
__global__ __launch_bounds__(256) void bag_kernel(
    const int* __restrict__ chars,
    const int* __restrict__ colors,
    const float* __restrict__ emb,
    float* __restrict__ out_bag,     // [B,64] as float
    float* __restrict__ out_emb)     // [B,64,20]
{
    __shared__ unsigned char present[GLYPH_DIM];     // 4 KB
    __shared__ unsigned bm[128];
    __shared__ unsigned wsum[4];
    __shared__ int bag_sh[MAX_LEN];
    __shared__ unsigned total_sh;

    const int tid = threadIdx.x;
    const int sample = blockIdx.x;
    const size_t base = (size_t)sample * HW;

    // zero presence bytes
    for (int i = tid; i < GLYPH_DIM / 4; i += 256)
        ((unsigned*)present)[i] = 0u;
    __syncthreads();

    // mark presence (plain byte stores; races benign)
    for (int i = tid; i < HW; i += 256) {
        int c  = __ldg(&chars [base + i]);
        int cl = __ldg(&colors[base + i]);
        present[(c << 4) + cl] = 1;
    }
    __syncthreads();

    // build 32-bit masks, popcount, warp scan
    unsigned myw = 0, mycnt = 0, incl = 0;
    if (tid < 128) {
        const unsigned* p = ((const unsigned*)present) + tid * 8;
        unsigned w = 0;
#pragma unroll
        for (int q = 0; q < 8; q++) {
            unsigned v = p[q];
            w |= ((v & 1u) | ((v >> 7) & 2u) | ((v >> 14) & 4u) | ((v >> 21) & 8u)) << (q * 4);
        }
        myw = w;
        bm[tid] = w;
        mycnt = __popc(w);
        incl = mycnt;
        unsigned lane = tid & 31;
#pragma unroll
        for (int d = 1; d < 32; d <<= 1) {
            unsigned n = __shfl_up_sync(0xffffffffu, incl, d);
            if (lane >= d) incl += n;
        }
        if (lane == 31) wsum[tid >> 5] = incl;
    }
    __syncthreads();

    unsigned excl = 0;
    if (tid < 128) {
        unsigned wid = tid >> 5;
        unsigned off = 0;
#pragma unroll
        for (int q = 0; q < 3; q++) if (q < (int)wid) off += wsum[q];
        excl = off + incl - mycnt;
        if (tid == 0) total_sh = wsum[0] + wsum[1] + wsum[2] + wsum[3];
    }
    __syncthreads();

    // emit first-64 ascending ids
    if (tid < 128 && excl < MAX_LEN) {
        unsigned m = myw, r = excl;
        while (m && r < MAX_LEN) {
            int b = __ffs(m) - 1;
            bag_sh[r++] = (tid << 5) + b;
            m &= m - 1;
        }
    }
    unsigned tot = total_sh;
    if (tid < MAX_LEN && (unsigned)tid >= tot)
        bag_sh[tid] = PAD_IDX;
    __syncthreads();

    // write bag (float to output, int to scratch)
    if (tid < MAX_LEN) {
        int g = bag_sh[tid];
        out_bag[(size_t)sample * MAX_LEN + tid] = (float)g;
        g_bag[sample * MAX_LEN + tid] = g;
    }

    // write emb rows: 64 * 20 = 1280 contiguous floats
    float* oe = out_emb + (size_t)sample * (MAX_LEN * EMB_DIM);
#pragma unroll
    for (int e = tid; e < MAX_LEN * EMB_DIM; e += 256) {
        int r = e / EMB_DIM;
        int k = e - r * EMB_DIM;
        int g = bag_sh[r];
        oe[e] = __ldg(&emb[(size_t)g * EMB_DIM + k]);
    }
}

// ---------------------------------------------------------------------------
// K2: RNN.  One warp per sample.  h in shared (double-buffered),
// W_hh row pairs in registers, packed f32x2 FMA.
// ---------------------------------------------------------------------------
__global__ __launch_bounds__(256) void rnn_kernel(
    const float* __restrict__ W_hh,
    float* __restrict__ out_h,
    int B)
{
    __shared__ float hs[8][2][HIDDEN];               // 2 KB

    const int gwarp = (blockIdx.x * blockDim.x + threadIdx.x) >> 5;
    const int lane  = threadIdx.x & 31;
    const int wloc  = threadIdx.x >> 5;
    if (gwarp >= B) return;

    // W_hh row for this lane, packed into 16 x 64-bit (pairs of f32)
    unsigned long long w2[16];
    {
        const unsigned long long* wp =
            (const unsigned long long*)(W_hh + lane * HIDDEN);
#pragma unroll
        for (int j = 0; j < 16; j++) w2[j] = __ldg(&wp[j]);
    }

    const int* bag = g_bag + gwarp * MAX_LEN;
    int id0 = __ldg(&bag[lane]);
    int id1 = __ldg(&bag[32 + lane]);

    hs[wloc][0][lane] = 0.f;
    float h = 0.f;
    int buf = 0;
    __syncwarp();

    for (int t = 0; t < MAX_LEN; t++) {
        int g = __shfl_sync(0xffffffffu, (t < 32) ? id0 : id1, t & 31);
        if (g >= PAD_IDX) break;                     // uniform across warp (bag sorted)

        float u = __ldg(&g_utab[g * HIDDEN + lane]); // includes both biases

        const unsigned long long* hp =
            (const unsigned long long*)&hs[wloc][buf][0];
        unsigned long long accA = 0ull, accB = 0ull;
#pragma unroll
        for (int j = 0; j < 16; j += 2) {
            asm("fma.rn.f32x2 %0, %1, %2, %3;"
                : "=l"(accA) : "l"(w2[j]),     "l"(hp[j]),     "l"(accA));
            asm("fma.rn.f32x2 %0, %1, %2, %3;"
                : "=l"(accB) : "l"(w2[j + 1]), "l"(hp[j + 1]), "l"(accB));
        }
        float a0, a1, b0, b1;
        asm("mov.b64 {%0,%1}, %2;" : "=f"(a0), "=f"(a1) : "l"(accA));
        asm("mov.b64 {%0,%1}, %2;" : "=f"(b0), "=f"(b1) : "l"(accB));

        float pre = u + (a0 + a1) + (b0 + b1);
        pre = fminf(fmaxf(pre, -15.f), 15.f);        // keep expf finite
        float e = __expf(2.f * pre);
        h = __fdividef(e - 1.f, e + 1.f);            // tanh

        buf ^= 1;
        hs[wloc][buf][lane] = h;
        __syncwarp();
    }

    out_h[(size_t)gwarp * HIDDEN + lane] = h;
}

// ---------------------------------------------------------------------------
// kernel_launch
// Inputs (metadata order): glyph_chars, glyph_colors, emb_table, W_ih, W_hh,
//                          b_ih, b_hh
// Output: concat(h [B,32], emb [B,64,20], bag [B,64]) as float32
// ---------------------------------------------------------------------------
extern "C" void kernel_launch(void* const* d_in, const int* in_sizes, int n_in,
                              void* d_out, int out_size)
{
    const int*   chars  = (const int*)  d_in[0];
    const int*   colors = (const int*)  d_in[1];
    const float* emb    = (const float*)d_in[2];
    const float* W_ih   = (const float*)d_in[3];
    const float* W_hh   = (const float*)d_in[4];
    const float* b_ih   = (const float*)d_in[5];
    const float* b_hh   = (const float*)d_in[6];

    const int B = in_sizes[0] / HW;

    float* out = (float*)d_out;
    const long long nh   = (long long)B * HIDDEN;
    const long long nemb = (long long)B * MAX_LEN * EMB_DIM;

    float* out_h   = out;
    float* out_emb = out + nh;
    float* out_bag = out + nh + nemb;

    // K0: u_table
    {
        int warps = GLYPH_DIM + 1;
        int blocks = (warps * 32 + 255) / 256;
        utab_kernel<<<blocks, 256>>>(emb, W_ih, b_ih, b_hh);
    }
    // K1: bag + emb + bag output
    bag_kernel<<<B, 256>>>(chars, colors, emb, out_bag, out_emb);
    // K2: RNN
    {
        int blocks = (B + 7) / 8;                    // 8 warps (samples) per block
        rnn_kernel<<<blocks, 256>>>(W_hh, out_h, B);
    }
}

// round 2
// speedup vs baseline: 1.1624x; 1.1624x over previous
#include <cuda_runtime.h>
#include <cuda_bf16.h>
#include <cstdint>

#define GLYPH_DIM 4096
#define PAD_IDX   4096
#define EMB_DIM   20
#define HIDDEN    32
#define MAX_LEN   64
#define HW        1659        // 21 * 79
#define WPB       4           // warps (samples) per block

// ---------------------------------------------------------------------------
// Device scratch
// ---------------------------------------------------------------------------
__device__ float g_utab[(GLYPH_DIM + 1) * HIDDEN];

// ---------------------------------------------------------------------------
// K0: u_table[g][i] = W_ih[i] . emb[g] + b_ih[i] + b_hh[i]   (4097 x 32)
// ---------------------------------------------------------------------------
__global__ void utab_kernel(const float* __restrict__ emb,
                            const float* __restrict__ W_ih,
                            const float* __restrict__ b_ih,
                            const float* __restrict__ b_hh)
{
    int warp = (blockIdx.x * blockDim.x + threadIdx.x) >> 5;
    int lane = threadIdx.x & 31;
    if (warp > GLYPH_DIM) return;

    const float4* wr = (const float4*)(W_ih + lane * EMB_DIM);   // 80B row, 16B aligned
    const float4* er = (const float4*)(emb + (size_t)warp * EMB_DIM);
    float4 w0 = __ldg(&wr[0]), w1 = __ldg(&wr[1]), w2 = __ldg(&wr[2]),
           w3 = __ldg(&wr[3]), w4 = __ldg(&wr[4]);
    float4 e0 = __ldg(&er[0]), e1 = __ldg(&er[1]), e2 = __ldg(&er[2]),
           e3 = __ldg(&er[3]), e4 = __ldg(&er[4]);

    float acc = __ldg(&b_ih[lane]) + __ldg(&b_hh[lane]);
    acc += w0.x*e0.x + w0.y*e0.y + w0.z*e0.z + w0.w*e0.w;
    acc += w1.x*e1.x + w1.y*e1.y + w1.z*e1.z + w1.w*e1.w;
    acc += w2.x*e2.x + w2.y*e2.y + w2.z*e2.z + w2.w*e2.w;
    acc += w3.x*e3.x + w3.y*e3.y + w3.z*e3.z + w3.w*e3.w;
    acc += w4.x*e4.x + w4.y*e4.y + w4.z*e4.z + w4.w*e4.w;

    g_utab[warp * HIDDEN + lane] = acc;
}

// ---------------------------------------------------------------------------
// Mega kernel: one warp per sample: presence -> bitmap -> bag -> emb -> RNN
// ---------------------------------------------------------------------------
__global__ __launch_bounds__(WPB * 32) void mega_kernel(
    const int* __restrict__ chars,
    const int* __restrict__ colors,
    const float* __restrict__ emb,
    const float* __restrict__ W_hh,
    float* __restrict__ out_h,
    float* __restrict__ out_emb,
    float* __restrict__ out_bag,
    int B)
{
    __shared__ __align__(16) unsigned char presence[WPB][GLYPH_DIM]; // 16 KB
    __shared__ int   bagsh[WPB][MAX_LEN + 4];
    __shared__ float hbuf [WPB][2][HIDDEN];

    const int lane = threadIdx.x & 31;
    const int w    = threadIdx.x >> 5;
    const int sample = blockIdx.x * WPB + w;
    if (sample >= B) return;

    // ---- Phase 1: zero presence (uint4 stores, conflict-free) ----
    {
        uint4 z = make_uint4(0u, 0u, 0u, 0u);
        uint4* p4 = (uint4*)presence[w];
#pragma unroll
        for (int i = 0; i < 8; i++) p4[lane + i * 32] = z;
    }
    __syncwarp();

    // ---- Phase 2: mark presence ----
    {
        const size_t base = (size_t)sample * HW;
        const int* cp = chars + base;
        const int* kp = colors + base;
#pragma unroll 4
        for (int i = lane; i < HW; i += 32) {
            int id = (__ldg(&cp[i]) << 4) + __ldg(&kp[i]);
            presence[w][id] = 1;
        }
    }
    __syncwarp();

    // ---- Phase 3: pack to bitmap words (word = m*32 + lane), count, scan ----
    unsigned mw[4];
    int      cnt[4];
    {
        const uint4* pq = (const uint4*)presence[w];
#pragma unroll
        for (int m = 0; m < 4; m++) {
            uint4 A = pq[64 * m + 2 * lane];
            uint4 Bv = pq[64 * m + 2 * lane + 1];
            unsigned word;
            unsigned n0 = ((A.x  * 0x01020408u) >> 24) & 0xFu;
            unsigned n1 = ((A.y  * 0x01020408u) >> 24) & 0xFu;
            unsigned n2 = ((A.z  * 0x01020408u) >> 24) & 0xFu;
            unsigned n3 = ((A.w  * 0x01020408u) >> 24) & 0xFu;
            unsigned n4 = ((Bv.x * 0x01020408u) >> 24) & 0xFu;
            unsigned n5 = ((Bv.y * 0x01020408u) >> 24) & 0xFu;
            unsigned n6 = ((Bv.z * 0x01020408u) >> 24) & 0xFu;
            unsigned n7 = ((Bv.w * 0x01020408u) >> 24) & 0xFu;
            word = n0 | (n1 << 4) | (n2 << 8) | (n3 << 12)
                 | (n4 << 16) | (n5 << 20) | (n6 << 24) | (n7 << 28);
            mw[m] = word;
            cnt[m] = __popc(word);
        }
    }

    int off[4];
    int runbase = 0;
#pragma unroll
    for (int m = 0; m < 4; m++) {
        int inc = cnt[m];
#pragma unroll
        for (int d = 1; d < 32; d <<= 1) {
            int n = __shfl_up_sync(0xffffffffu, inc, d);
            if (lane >= d) inc += n;
        }
        off[m] = runbase + inc - cnt[m];
        runbase += __shfl_sync(0xffffffffu, inc, 31);
    }
    const int total = runbase;
    const int steps = total < MAX_LEN ? total : MAX_LEN;

    // ---- Phase 4: emit ascending ids, pad with PAD_IDX ----
#pragma unroll
    for (int m = 0; m < 4; m++) {
        unsigned mm = mw[m];
        int o = off[m];
        int base = 1024 * m + 32 * lane;
        while (mm && o < MAX_LEN) {
            int b = __ffs(mm) - 1;
            bagsh[w][o++] = base + b;
            mm &= mm - 1;
        }
    }
#pragma unroll
    for (int i = lane; i < MAX_LEN; i += 32)
        if (i >= total) bagsh[w][i] = PAD_IDX;
    __syncwarp();

    // ---- Phase 5: outputs (bag as float, gathered emb rows as float4) ----
    if (lane < 16) {
        float4 bf;
        bf.x = (float)bagsh[w][lane * 4 + 0];
        bf.y = (float)bagsh[w][lane * 4 + 1];
        bf.z = (float)bagsh[w][lane * 4 + 2];
        bf.w = (float)bagsh[w][lane * 4 + 3];
        ((float4*)(out_bag + (size_t)sample * MAX_LEN))[lane] = bf;
    }
    {
        float* dstbase = out_emb + (size_t)sample * (MAX_LEN * EMB_DIM);
#pragma unroll
        for (int rr = 0; rr < 2; rr++) {
            int r = 2 * lane + rr;
            int g = bagsh[w][r];
            const float4* src = (const float4*)(emb + (size_t)g * EMB_DIM);
            float4* dst = (float4*)(dstbase + r * EMB_DIM);
#pragma unroll
            for (int k = 0; k < 5; k++) dst[k] = __ldg(&src[k]);
        }
    }

    // ---- Phase 6: RNN ----
    unsigned long long w2[16];
    {
        const unsigned long long* wp = (const unsigned long long*)(W_hh + lane * HIDDEN);
#pragma unroll
        for (int j = 0; j < 16; j++) w2[j] = __ldg(&wp[j]);
    }

    hbuf[w][0][lane] = 0.f;
    float h = 0.f;
    int buf = 0;
    __syncwarp();

    // prefetch u for step 0
    float u_next = 0.f;
    if (steps > 0) {
        int g0 = bagsh[w][0];
        u_next = __ldg(&g_utab[g0 * HIDDEN + lane]);
    }

    for (int t = 0; t < steps; t++) {
        float u = u_next;
        {
            int tn = t + 1 < steps ? t + 1 : t;
            int gn = bagsh[w][tn];
            u_next = __ldg(&g_utab[gn * HIDDEN + lane]);
        }

        const unsigned long long* hp = (const unsigned long long*)&hbuf[w][buf][0];
        unsigned long long accA = 0ull, accB = 0ull;
#pragma unroll
        for (int j = 0; j < 16; j += 2) {
            asm("fma.rn.f32x2 %0, %1, %2, %3;"
                : "=l"(accA) : "l"(w2[j]),     "l"(hp[j]),     "l"(accA));
            asm("fma.rn.f32x2 %0, %1, %2, %3;"
                : "=l"(accB) : "l"(w2[j + 1]), "l"(hp[j + 1]), "l"(accB));
        }
        float a0, a1, b0, b1;
        asm("mov.b64 {%0,%1}, %2;" : "=f"(a0), "=f"(a1) : "l"(accA));
        asm("mov.b64 {%0,%1}, %2;" : "=f"(b0), "=f"(b1) : "l"(accB));

        float pre = u + (a0 + a1) + (b0 + b1);
        pre = fminf(fmaxf(pre, -15.f), 15.f);
        float e = __expf(2.f * pre);
        h = __fdividef(e - 1.f, e + 1.f);

        buf ^= 1;
        hbuf[w][buf][lane] = h;
        __syncwarp();
    }

    out_h[(size_t)sample * HIDDEN + lane] = h;
}

// ---------------------------------------------------------------------------
// kernel_launch
// Inputs: glyph_chars, glyph_colors, emb_table, W_ih, W_hh, b_ih, b_hh
// Output: concat(h [B,32], emb [B,64,20], bag [B,64]) float32
// ---------------------------------------------------------------------------
extern "C" void kernel_launch(void* const* d_in, const int* in_sizes, int n_in,
                              void* d_out, int out_size)
{
    const int*   chars  = (const int*)  d_in[0];
    const int*   colors = (const int*)  d_in[1];
    const float* emb    = (const float*)d_in[2];
    const float* W_ih   = (const float*)d_in[3];
    const float* W_hh   = (const float*)d_in[4];
    const float* b_ih   = (const float*)d_in[5];
    const float* b_hh   = (const float*)d_in[6];

    const int B = in_sizes[0] / HW;

    float* out = (float*)d_out;
    const long long nh   = (long long)B * HIDDEN;
    const long long nemb = (long long)B * MAX_LEN * EMB_DIM;

    float* out_h   = out;
    float* out_emb = out + nh;
    float* out_bag = out + nh + nemb;

    {
        int warps  = GLYPH_DIM + 1;
        int blocks = (warps * 32 + 255) / 256;
        utab_kernel<<<blocks, 256>>>(emb, W_ih, b_ih, b_hh);
    }
    {
        int blocks = (B + WPB - 1) / WPB;
        mega_kernel<<<blocks, WPB * 32>>>(chars, colors, emb, W_hh,
                                          out_h, out_emb, out_bag, B);
    }
}